// round 9
// baseline (speedup 1.0000x reference)
#include <cuda_runtime.h>
#include <cuda_bf16.h>
#include <cstdint>

typedef unsigned long long u64;

#define Bn 256
#define Tn 256
#define Sn 20
#define NROWS (Bn*Tn)   // 65536

__device__ float g_zx[NROWS * 96];   // zx[row][96] = h_inner[row] @ Wo + bo

// ---------- packed f32x2 helpers (outer kernel) ----------
__device__ __forceinline__ u64 ffma2(u64 a, u64 b, u64 c){
    u64 d;
    asm("fma.rn.f32x2 %0, %1, %2, %3;" : "=l"(d) : "l"(a), "l"(b), "l"(c));
    return d;
}
__device__ __forceinline__ u64 add2(u64 a, u64 b){
    u64 d;
    asm("add.rn.f32x2 %0, %1, %2;" : "=l"(d) : "l"(a), "l"(b));
    return d;
}
__device__ __forceinline__ u64 pk2(float lo, float hi){
    u64 r; asm("mov.b64 %0, {%1, %2};" : "=l"(r) : "f"(lo), "f"(hi)); return r;
}
__device__ __forceinline__ void up2(u64 v, float& lo, float& hi){
    asm("mov.b64 {%0, %1}, %2;" : "=f"(lo), "=f"(hi) : "l"(v));
}

// ---------- activations ----------
__device__ __forceinline__ float tanha(float x){
    float r; asm("tanh.approx.f32 %0, %1;" : "=f"(r) : "f"(x)); return r;
}
__device__ __forceinline__ float sigt(float x){
    return fmaf(0.5f, tanha(0.5f * x), 0.5f);
}

// ---------- smem / swizzle ----------
__device__ __forceinline__ uint32_t smem_to_u32(const void* p){
    uint32_t a;
    asm("{ .reg .u64 t; cvta.to.shared.u64 t, %1; cvt.u32.u64 %0, t; }"
        : "=r"(a) : "l"(p));
    return a;
}
#define SWZ(bo) ((bo) ^ (((bo) >> 3) & 0x70))

// ---------- mma.sync / ldmatrix (baseline PTX, compiles for sm_103) ----------
#define MMA_BF16(d, a, b0v, b1v) \
    asm volatile("mma.sync.aligned.m16n8k16.row.col.f32.bf16.bf16.f32 " \
        "{%0,%1,%2,%3}, {%4,%5,%6,%7}, {%8,%9}, {%0,%1,%2,%3};" \
        : "+f"((d)[0]), "+f"((d)[1]), "+f"((d)[2]), "+f"((d)[3]) \
        : "r"((a)[0]), "r"((a)[1]), "r"((a)[2]), "r"((a)[3]), "r"(b0v), "r"(b1v))

#define LDSM4(r, addr) \
    asm volatile("ldmatrix.sync.aligned.m8n8.x4.shared.b16 {%0,%1,%2,%3}, [%4];" \
        : "=r"((r)[0]), "=r"((r)[1]), "=r"((r)[2]), "=r"((r)[3]) : "r"(addr))

// SMEM layout (bytes); A/B tiles: [128][64] bf16 = 128B rows, SW128-swizzled
#define OFF_AH 0
#define OFF_AL 16384
#define OFF_BH 32768
#define OFF_BL 49152
#define OFF_WO 65536    // 32*96 f32 = 12288
#define OFF_BO 77824    // 96 f32
#define SMEM_SZ 78208

// =====================================================================
// Inner LSTM via warp-level bf16 mma.sync. 512 blocks x 256 thr (8 warps).
// Warp w owns rows 16w..16w+15 -- fully independent (no block sync in loop).
// Per step: D[16x128] = A[16x48] x B[48x128]. 4-product bf16 hi/lo split on
// the h block (AhBh+AhBl+AlBh+AlBl), 3-product on the x/1 block -> rel err
// ~1e-6 per z. B cols: [i,f x32u | g,o x32u] interleaved so every lane holds
// all 4 gates of its units in D frags. h written back bf16 hi/lo into A.
// =====================================================================
__global__ void __launch_bounds__(256) inner_mma(
    const float* __restrict__ x,  const float* __restrict__ Wi,
    const float* __restrict__ Ui, const float* __restrict__ bi,
    const float* __restrict__ Wo, const float* __restrict__ bo)
{
    extern __shared__ char smc[];
    const uint32_t sb = smem_to_u32(smc);
    const int tid  = threadIdx.x;
    const int wid  = tid >> 5;
    const int lane = tid & 31;
    const int q    = lane & 3;
    const int rr   = lane >> 2;            // 0..7
    const int wrow0 = wid * 16;            // warp's first local row

    // --- build B tiles (hi/lo): n-row = permuted gate col, k = [Ui | Wi | bi | 0] ---
    for (int idx = tid; idx < 128 * 64; idx += 256){
        int n = idx >> 6, k = idx & 63;
        int u, g;
        if (n < 64){ u = n >> 1; g = n & 1; }               // i,f block
        else       { u = (n - 64) >> 1; g = 2 + (n & 1); }  // g,o block
        int col = g * 32 + u;
        float w = 0.f;
        if (k < 32)       w = Ui[k * 128 + col];
        else if (k == 32) w = Wi[col];
        else if (k == 33) w = bi[col];
        __nv_bfloat16 wh = __float2bfloat16(w);
        float wl = w - __bfloat162float(wh);
        uint32_t off = SWZ((uint32_t)(n * 128 + k * 2));
        *(__nv_bfloat16*)(smc + OFF_BH + off) = wh;
        *(__nv_bfloat16*)(smc + OFF_BL + off) = __float2bfloat16(wl);
    }
    // --- zero A tiles (h0=0, pads=0) ---
    for (int i = tid; i < 4096; i += 256){
        ((uint32_t*)(smc + OFF_AH))[i] = 0u;
        ((uint32_t*)(smc + OFF_AL))[i] = 0u;
    }
    // --- stage Wo/bo for zx epilogue ---
    {
        float* wos = (float*)(smc + OFF_WO);
        for (int i = tid; i < 32 * 96; i += 256) wos[i] = Wo[i];
        float* bos = (float*)(smc + OFF_BO);
        if (tid < 96) bos[tid] = bo[tid];
    }
    __syncthreads();

    // --- loop-invariant ldmatrix addresses ---
    const uint32_t aRow  = wrow0 + (lane & 15);
    const uint32_t aByte = (uint32_t)(lane >> 4) << 4;
    const uint32_t aoffH = sb + OFF_AH + SWZ(aRow * 128 + aByte);
    const uint32_t aoffL = aoffH + 16384;
    uint32_t boffH[8];
    {
        uint32_t nrow = ((uint32_t)(lane >> 4) << 3) + (lane & 7);
        uint32_t bbyte = ((uint32_t)((lane >> 3) & 1)) << 4;
        #pragma unroll
        for (int np = 0; np < 8; np++)
            boffH[np] = sb + OFF_BH + SWZ((16 * np + nrow) * 128 + bbyte);
    }
    const uint32_t xoff = SWZ((uint32_t)((wrow0 + (lane & 15)) * 128 + 64));

    const long grow = (long)blockIdx.x * 128 + wrow0 + (lane & 15);
    const float* xrow = x + grow * Sn;
    float xnext = __ldg(xrow);

    float cst[16];
    #pragma unroll
    for (int i = 0; i < 16; i++) cst[i] = 0.f;

    const int row0 = wrow0 + rr;
    const int row1 = row0 + 8;

    #pragma unroll 1
    for (int s = 0; s < Sn; s++){
        if (lane < 16){
            float xv = xnext;
            int sp = (s + 1 < Sn) ? s + 1 : s;
            xnext = __ldg(xrow + sp);
            __nv_bfloat16 xh = __float2bfloat16(xv);
            float xl = xv - __bfloat162float(xh);
            uint32_t hi = (0x3F80u << 16) | (uint32_t)__bfloat16_as_ushort(xh);
            uint32_t lo = (uint32_t)__bfloat16_as_ushort(__float2bfloat16(xl));
            *(uint32_t*)(smc + OFF_AH + xoff) = hi;
            *(uint32_t*)(smc + OFF_AL + xoff) = lo;
        }
        __syncwarp();

        uint32_t ah[3][4], al[3][4];
        #pragma unroll
        for (int kc = 0; kc < 3; kc++){
            LDSM4(ah[kc], aoffH + 32 * kc);
            LDSM4(al[kc], aoffL + 32 * kc);
        }
        __syncwarp();

        #pragma unroll
        for (int npp = 0; npp < 4; npp++){
            float dIF0[4] = {0.f,0.f,0.f,0.f};
            float dIF1[4] = {0.f,0.f,0.f,0.f};
            float dGO0[4] = {0.f,0.f,0.f,0.f};
            float dGO1[4] = {0.f,0.f,0.f,0.f};
            #pragma unroll
            for (int kc = 0; kc < 3; kc++){
                uint32_t bIFh[4], bIFl[4], bGOh[4], bGOl[4];
                LDSM4(bIFh, boffH[npp]     + 32 * kc);
                LDSM4(bIFl, boffH[npp]     + 16384 + 32 * kc);
                LDSM4(bGOh, boffH[npp + 4] + 32 * kc);
                LDSM4(bGOl, boffH[npp + 4] + 16384 + 32 * kc);
                MMA_BF16(dIF0, ah[kc], bIFh[0], bIFh[1]);
                MMA_BF16(dIF0, ah[kc], bIFl[0], bIFl[1]);
                MMA_BF16(dIF0, al[kc], bIFh[0], bIFh[1]);
                MMA_BF16(dIF1, ah[kc], bIFh[2], bIFh[3]);
                MMA_BF16(dIF1, ah[kc], bIFl[2], bIFl[3]);
                MMA_BF16(dIF1, al[kc], bIFh[2], bIFh[3]);
                MMA_BF16(dGO0, ah[kc], bGOh[0], bGOh[1]);
                MMA_BF16(dGO0, ah[kc], bGOl[0], bGOl[1]);
                MMA_BF16(dGO0, al[kc], bGOh[0], bGOh[1]);
                MMA_BF16(dGO1, ah[kc], bGOh[2], bGOh[3]);
                MMA_BF16(dGO1, ah[kc], bGOl[2], bGOl[3]);
                MMA_BF16(dGO1, al[kc], bGOh[2], bGOh[3]);
                if (kc < 2){   // Al*Bl for the h block: kills the 2^-18 term
                    MMA_BF16(dIF0, al[kc], bIFl[0], bIFl[1]);
                    MMA_BF16(dIF1, al[kc], bIFl[2], bIFl[3]);
                    MMA_BF16(dGO0, al[kc], bGOl[0], bGOl[1]);
                    MMA_BF16(dGO1, al[kc], bGOl[2], bGOl[3]);
                }
            }
            const int vA = 8 * npp + q;
            const int vB = vA + 4;
            #pragma unroll
            for (int e = 0; e < 4; e++){
                const float* dif = (e < 2) ? dIF0 : dIF1;
                const float* dgo = (e < 2) ? dGO0 : dGO1;
                int half = (e & 1) * 2;
                float zi = dif[half], zf = dif[half + 1];
                float zg = dgo[half], zo = dgo[half + 1];
                float ii = sigt(zi), ff = sigt(zf);
                float gg = tanha(zg), oo = sigt(zo);
                float cv = ff * cst[npp * 4 + e] + ii * gg;
                cst[npp * 4 + e] = cv;
                float h = oo * tanha(cv);
                int v  = (e < 2) ? vA : vB;
                int rw = (e & 1) ? row1 : row0;
                uint32_t off = SWZ((uint32_t)(rw * 128 + v * 2));
                __nv_bfloat16 hh = __float2bfloat16(h);
                float hl = h - __bfloat162float(hh);
                *(__nv_bfloat16*)(smc + OFF_AH + off) = hh;
                *(__nv_bfloat16*)(smc + OFF_AL + off) = __float2bfloat16(hl);
            }
        }
        __syncwarp();
    }

    // --- zx epilogue: h = hi + lo; warp-local rows only ---
    __syncwarp();
    {
        const int row = tid >> 1;
        const int cg  = tid & 1;
        const float* wos = (float*)(smc + OFF_WO);
        const float* bos = (float*)(smc + OFF_BO);
        float4 acc[12];
        #pragma unroll
        for (int j = 0; j < 12; j++)
            acc[j] = *(const float4*)(bos + cg * 48 + j * 4);
        #pragma unroll 4
        for (int k = 0; k < 32; k++){
            uint32_t off = SWZ((uint32_t)(row * 128 + k * 2));
            float hk = __bfloat162float(*(__nv_bfloat16*)(smc + OFF_AH + off))
                     + __bfloat162float(*(__nv_bfloat16*)(smc + OFF_AL + off));
            const float4* wp = (const float4*)(wos + k * 96 + cg * 48);
            #pragma unroll
            for (int j = 0; j < 12; j++){
                float4 w = wp[j];
                acc[j].x = fmaf(hk, w.x, acc[j].x);
                acc[j].y = fmaf(hk, w.y, acc[j].y);
                acc[j].z = fmaf(hk, w.z, acc[j].z);
                acc[j].w = fmaf(hk, w.w, acc[j].w);
            }
        }
        float* zp = g_zx + ((size_t)blockIdx.x * 128 + row) * 96 + cg * 48;
        #pragma unroll
        for (int j = 0; j < 12; j++) *(float4*)(zp + j * 4) = acc[j];
    }
}

// =====================================================================
// Outer LSTM + dense head: TWO rows per warp (rows b, b+128), 128 blocks.
// Interleaved recurrences double ILP at same chain depth. Shared register
// weights; predicated state carry implements the ragged-length mask.
// =====================================================================
__device__ __forceinline__ void outer_step2(
    float& hA, float& cA, float& hB, float& cB,
    u64 zAa, u64 zBa, u64 zAb, u64 zBb,
    const u64* w_if, const u64* w_go, bool actA, bool actB)
{
    u64 aA0 = zAa, aA1 = 0ULL, bA0 = zBa, bA1 = 0ULL;
    u64 aB0 = zAb, aB1 = 0ULL, bB0 = zBb, bB1 = 0ULL;
    #pragma unroll
    for (int j = 0; j < 12; j++){
        float hA0 = __shfl_sync(0xffffffffu, hA, j);
        float hA1 = __shfl_sync(0xffffffffu, hA, j + 12);
        float hB0 = __shfl_sync(0xffffffffu, hB, j);
        float hB1 = __shfl_sync(0xffffffffu, hB, j + 12);
        u64 HA0 = pk2(hA0, hA0), HA1 = pk2(hA1, hA1);
        u64 HB0 = pk2(hB0, hB0), HB1 = pk2(hB1, hB1);
        aA0 = ffma2(HA0, w_if[j],      aA0);
        bA0 = ffma2(HA0, w_go[j],      bA0);
        aA1 = ffma2(HA1, w_if[j + 12], aA1);
        bA1 = ffma2(HA1, w_go[j + 12], bA1);
        aB0 = ffma2(HB0, w_if[j],      aB0);
        bB0 = ffma2(HB0, w_go[j],      bB0);
        aB1 = ffma2(HB1, w_if[j + 12], aB1);
        bB1 = ffma2(HB1, w_go[j + 12], bB1);
    }
    {
        u64 zAf = add2(aA0, aA1), zBf = add2(bA0, bA1);
        float zi, zf, zg, zo;
        up2(zAf, zi, zf); up2(zBf, zg, zo);
        float fi = sigt(zi), ff = sigt(zf), gg = tanha(zg), oo = sigt(zo);
        float cn = fmaf(ff, cA, fi * gg);
        float hn = oo * tanha(cn);
        cA = actA ? cn : cA;
        hA = actA ? hn : hA;
    }
    {
        u64 zAf = add2(aB0, aB1), zBf = add2(bB0, bB1);
        float zi, zf, zg, zo;
        up2(zAf, zi, zf); up2(zBf, zg, zo);
        float fi = sigt(zi), ff = sigt(zf), gg = tanha(zg), oo = sigt(zo);
        float cn = fmaf(ff, cB, fi * gg);
        float hn = oo * tanha(cn);
        cB = actB ? cn : cB;
        hB = actB ? hn : hB;
    }
}

__global__ void __launch_bounds__(32) outer_kernel(
    const int*   __restrict__ lengths,
    const float* __restrict__ Uo,
    const float* __restrict__ Wd,
    const float* __restrict__ bd,
    float*       __restrict__ out)
{
    const int l  = threadIdx.x;
    const int la = (l < 24) ? l : 0;
    const int bA = blockIdx.x;
    const int bB = blockIdx.x + 128;

    u64 w_if[24], w_go[24];
    #pragma unroll
    for (int k = 0; k < 24; k++){
        const float* row = Uo + k * 96;
        w_if[k] = pk2(__ldg(row + la),      __ldg(row + 24 + la));
        w_go[k] = pk2(__ldg(row + 48 + la), __ldg(row + 72 + la));
    }

    const int lenA = lengths[bA];
    const int lenB = lengths[bB];
    const int lenM = (lenA > lenB) ? lenA : lenB;
    const float* zrA = g_zx + (size_t)bA * Tn * 96;
    const float* zrB = g_zx + (size_t)bB * Tn * 96;

    // static two-slot prefetch per row
    u64 Aa0, Ba0, Aa1, Ba1, Ab0, Bb0, Ab1, Bb1;
    Aa0 = pk2(zrA[la], zrA[24 + la]);
    Ba0 = pk2(zrA[48 + la], zrA[72 + la]);
    Ab0 = pk2(zrB[la], zrB[24 + la]);
    Bb0 = pk2(zrB[48 + la], zrB[72 + la]);
    {
        const float* z1 = zrA + ((lenA > 1) ? 96 : 0);
        Aa1 = pk2(z1[la], z1[24 + la]);
        Ba1 = pk2(z1[48 + la], z1[72 + la]);
        const float* z2 = zrB + ((lenB > 1) ? 96 : 0);
        Ab1 = pk2(z2[la], z2[24 + la]);
        Bb1 = pk2(z2[48 + la], z2[72 + la]);
    }

    float hA = 0.f, cA = 0.f, hB = 0.f, cB = 0.f;
    int t = 0;
    while (t < lenM){
        {
            u64 zAa = Aa0, zBa = Ba0, zAb = Ab0, zBb = Bb0;
            int tpA = (t + 2 < lenA) ? t + 2 : lenA - 1;
            int tpB = (t + 2 < lenB) ? t + 2 : lenB - 1;
            const float* zqA = zrA + (size_t)tpA * 96;
            const float* zqB = zrB + (size_t)tpB * 96;
            Aa0 = pk2(zqA[la], zqA[24 + la]);
            Ba0 = pk2(zqA[48 + la], zqA[72 + la]);
            Ab0 = pk2(zqB[la], zqB[24 + la]);
            Bb0 = pk2(zqB[48 + la], zqB[72 + la]);
            outer_step2(hA, cA, hB, cB, zAa, zBa, zAb, zBb,
                        w_if, w_go, t < lenA, t < lenB);
        }
        t++;
        if (t >= lenM) break;
        {
            u64 zAa = Aa1, zBa = Ba1, zAb = Ab1, zBb = Bb1;
            int tpA = (t + 2 < lenA) ? t + 2 : lenA - 1;
            int tpB = (t + 2 < lenB) ? t + 2 : lenB - 1;
            const float* zqA = zrA + (size_t)tpA * 96;
            const float* zqB = zrB + (size_t)tpB * 96;
            Aa1 = pk2(zqA[la], zqA[24 + la]);
            Ba1 = pk2(zqA[48 + la], zqA[72 + la]);
            Ab1 = pk2(zqB[la], zqB[24 + la]);
            Bb1 = pk2(zqB[48 + la], zqB[72 + la]);
            outer_step2(hA, cA, hB, cB, zAa, zBa, zAb, zBb,
                        w_if, w_go, t < lenA, t < lenB);
        }
        t++;
    }

    // dense sigmoid head for both rows
    float pA = (l < 24) ? hA * __ldg(Wd + la) : 0.f;
    float pB = (l < 24) ? hB * __ldg(Wd + la) : 0.f;
    #pragma unroll
    for (int off = 16; off; off >>= 1){
        pA += __shfl_xor_sync(0xffffffffu, pA, off);
        pB += __shfl_xor_sync(0xffffffffu, pB, off);
    }
    if (l == 0){
        out[bA] = fmaf(0.5f, tanha(0.5f * (pA + bd[0])), 0.5f);
        out[bB] = fmaf(0.5f, tanha(0.5f * (pB + bd[0])), 0.5f);
    }
}

extern "C" void kernel_launch(void* const* d_in, const int* in_sizes, int n_in,
                              void* d_out, int out_size)
{
    const float* x       = (const float*)d_in[0];
    const int*   lengths = (const int*)  d_in[1];
    const float* Wi      = (const float*)d_in[2];
    const float* Ui      = (const float*)d_in[3];
    const float* bi      = (const float*)d_in[4];
    const float* Wo      = (const float*)d_in[5];
    const float* Uo      = (const float*)d_in[6];
    const float* bo      = (const float*)d_in[7];
    const float* Wd      = (const float*)d_in[8];
    const float* bd      = (const float*)d_in[9];
    float* out = (float*)d_out;

    cudaFuncSetAttribute(inner_mma,
                         cudaFuncAttributeMaxDynamicSharedMemorySize, SMEM_SZ);

    inner_mma<<<512, 256, SMEM_SZ>>>(x, Wi, Ui, bi, Wo, bo);
    outer_kernel<<<128, 32>>>(lengths, Uo, Wd, bd, out);
}

// round 10
// speedup vs baseline: 1.2677x; 1.2677x over previous
#include <cuda_runtime.h>
#include <cuda_fp16.h>
#include <cstdint>

typedef unsigned long long u64;

#define Bn 256
#define Tn 256
#define Sn 20
#define NROWS (Bn*Tn)   // 65536

__device__ float g_zx[NROWS * 96];   // zx[row][96] = h_inner[row] @ Wo + bo
__device__ __align__(16) unsigned char g_btiles[32768];  // Bh|Bl fp16, swizzled

// ---------- packed f32x2 helpers (outer kernel) ----------
__device__ __forceinline__ u64 ffma2(u64 a, u64 b, u64 c){
    u64 d;
    asm("fma.rn.f32x2 %0, %1, %2, %3;" : "=l"(d) : "l"(a), "l"(b), "l"(c));
    return d;
}
__device__ __forceinline__ u64 add2(u64 a, u64 b){
    u64 d;
    asm("add.rn.f32x2 %0, %1, %2;" : "=l"(d) : "l"(a), "l"(b));
    return d;
}
__device__ __forceinline__ u64 pk2(float lo, float hi){
    u64 r; asm("mov.b64 %0, {%1, %2};" : "=l"(r) : "f"(lo), "f"(hi)); return r;
}
__device__ __forceinline__ void up2(u64 v, float& lo, float& hi){
    asm("mov.b64 {%0, %1}, %2;" : "=f"(lo), "=f"(hi) : "l"(v));
}

// ---------- activations ----------
__device__ __forceinline__ float tanha(float x){
    float r; asm("tanh.approx.f32 %0, %1;" : "=f"(r) : "f"(x)); return r;
}
__device__ __forceinline__ float sigt(float x){
    return fmaf(0.5f, tanha(0.5f * x), 0.5f);
}

// ---------- smem / swizzle ----------
__device__ __forceinline__ uint32_t smem_to_u32(const void* p){
    uint32_t a;
    asm("{ .reg .u64 t; cvta.to.shared.u64 t, %1; cvt.u32.u64 %0, t; }"
        : "=r"(a) : "l"(p));
    return a;
}
#define SWZ(bo) ((bo) ^ (((bo) >> 3) & 0x70))

// ---------- mma.sync / ldmatrix (fp16, baseline PTX) ----------
#define MMA_F16(d, a, b0v, b1v) \
    asm volatile("mma.sync.aligned.m16n8k16.row.col.f32.f16.f16.f32 " \
        "{%0,%1,%2,%3}, {%4,%5,%6,%7}, {%8,%9}, {%0,%1,%2,%3};" \
        : "+f"((d)[0]), "+f"((d)[1]), "+f"((d)[2]), "+f"((d)[3]) \
        : "r"((a)[0]), "r"((a)[1]), "r"((a)[2]), "r"((a)[3]), "r"(b0v), "r"(b1v))

#define LDSM4(r, addr) \
    asm volatile("ldmatrix.sync.aligned.m8n8.x4.shared.b16 {%0,%1,%2,%3}, [%4];" \
        : "=r"((r)[0]), "=r"((r)[1]), "=r"((r)[2]), "=r"((r)[3]) : "r"(addr))

// SMEM layout (bytes)
#define OFF_AH 0        // A hi [64][64] fp16, 8KB
#define OFF_AL 8192     // A lo, 8KB
#define OFF_BH 16384    // B hi [128][64] fp16, 16KB (Wo fp32 reused here post-loop)
#define OFF_BL 32768    // B lo, 16KB
#define OFF_BO 49152    // bo, 96 f32
#define SMEM_SZ 49664

// =====================================================================
// B-tile prep: build the loop-invariant weight tiles (fp16 hi/lo, SW128-
// swizzled) ONCE in gmem; inner blocks memcpy them (16 LDG.128 iters).
// n-row = permuted gate col ([i,f]x32u | [g,o]x32u), k = [Ui | Wi | bi | 0].
// =====================================================================
__global__ void bprep(const float* __restrict__ Wi,
                      const float* __restrict__ Ui,
                      const float* __restrict__ bi)
{
    int idx = blockIdx.x * 256 + threadIdx.x;
    if (idx >= 8192) return;
    int n = idx >> 6, k = idx & 63;
    int u, g;
    if (n < 64){ u = n >> 1; g = n & 1; }
    else       { u = (n - 64) >> 1; g = 2 + (n & 1); }
    int col = g * 32 + u;
    float w = 0.f;
    if (k < 32)       w = Ui[k * 128 + col];
    else if (k == 32) w = Wi[col];
    else if (k == 33) w = bi[col];
    __half wh = __float2half(w);
    __half wl = __float2half(w - __half2float(wh));
    uint32_t off = SWZ((uint32_t)(n * 128 + k * 2));
    *(__half*)(g_btiles + off)         = wh;
    *(__half*)(g_btiles + 16384 + off) = wl;
}

// =====================================================================
// Inner LSTM via warp-level fp16 mma.sync. 1024 blocks x 128 thr (4 warps),
// 64 rows/block (finer wave granularity: max 7x64=448 rows/SM vs 512).
// Warp w owns rows 16w..16w+15 -- independent (no block sync in loop).
// Per step: D[16x128] = A[16x48] x B[48x128], 3-product fp16 hi/lo split
// (pair captures ~22 mantissa bits -> per-z err ~1e-6). h written back
// fp16 hi/lo into A. Epilogue: zx = h @ Wo + bo (Wo reuses BH smem).
// =====================================================================
__global__ void __launch_bounds__(128, 4) inner_mma(
    const float* __restrict__ x,
    const float* __restrict__ Wo, const float* __restrict__ bo)
{
    extern __shared__ char smc[];
    const uint32_t sb = smem_to_u32(smc);
    const int tid  = threadIdx.x;
    const int wid  = tid >> 5;
    const int lane = tid & 31;
    const int q    = lane & 3;
    const int rr   = lane >> 2;            // 0..7
    const int wrow0 = wid * 16;            // warp's first local row (0..48)

    // --- copy prebuilt B tiles (32KB contiguous: BH then BL) ---
    {
        const uint4* src = (const uint4*)g_btiles;
        uint4* dst = (uint4*)(smc + OFF_BH);
        for (int i = tid; i < 2048; i += 128) dst[i] = src[i];
    }
    // --- zero A tiles (h0=0, pads=0): 16KB = 4096 u32 ---
    for (int i = tid; i < 4096; i += 128)
        ((uint32_t*)(smc + OFF_AH))[i] = 0u;
    // --- stage bo ---
    if (tid < 96) ((float*)(smc + OFF_BO))[tid] = bo[tid];
    __syncthreads();

    // --- loop-invariant ldmatrix addresses ---
    const uint32_t aRow  = wrow0 + (lane & 15);
    const uint32_t aByte = (uint32_t)(lane >> 4) << 4;
    const uint32_t aoffH = sb + OFF_AH + SWZ(aRow * 128 + aByte);
    const uint32_t aoffL = aoffH + 8192;
    uint32_t boffH[8];
    {
        uint32_t nrow = ((uint32_t)(lane >> 4) << 3) + (lane & 7);
        uint32_t bbyte = ((uint32_t)((lane >> 3) & 1)) << 4;
        #pragma unroll
        for (int np = 0; np < 8; np++)
            boffH[np] = sb + OFF_BH + SWZ((16 * np + nrow) * 128 + bbyte);
    }
    const uint32_t xoff = SWZ((uint32_t)((wrow0 + (lane & 15)) * 128 + 64));

    const long grow = (long)blockIdx.x * 64 + wrow0 + (lane & 15);
    const float* xrow = x + grow * Sn;
    float xnext = __ldg(xrow);

    float cst[16];
    #pragma unroll
    for (int i = 0; i < 16; i++) cst[i] = 0.f;

    const int row0 = wrow0 + rr;
    const int row1 = row0 + 8;

    #pragma unroll 1
    for (int s = 0; s < Sn; s++){
        if (lane < 16){
            float xv = xnext;
            int sp = (s + 1 < Sn) ? s + 1 : s;
            xnext = __ldg(xrow + sp);
            __half xh = __float2half(xv);
            __half xl = __float2half(xv - __half2float(xh));
            // low addr = k=32 (x), high = k=33 (one = fp16 0x3C00)
            uint32_t hi = (0x3C00u << 16) | (uint32_t)__half_as_ushort(xh);
            uint32_t lo = (uint32_t)__half_as_ushort(xl);
            *(uint32_t*)(smc + OFF_AH + xoff) = hi;
            *(uint32_t*)(smc + OFF_AL + xoff) = lo;
        }
        __syncwarp();

        uint32_t ah[3][4], al[3][4];
        #pragma unroll
        for (int kc = 0; kc < 3; kc++){
            LDSM4(ah[kc], aoffH + 32 * kc);
            LDSM4(al[kc], aoffL + 32 * kc);
        }
        __syncwarp();

        #pragma unroll
        for (int npp = 0; npp < 4; npp++){
            float dIF0[4] = {0.f,0.f,0.f,0.f};
            float dIF1[4] = {0.f,0.f,0.f,0.f};
            float dGO0[4] = {0.f,0.f,0.f,0.f};
            float dGO1[4] = {0.f,0.f,0.f,0.f};
            #pragma unroll
            for (int kc = 0; kc < 3; kc++){
                uint32_t bIFh[4], bIFl[4], bGOh[4], bGOl[4];
                LDSM4(bIFh, boffH[npp]     + 32 * kc);
                LDSM4(bIFl, boffH[npp]     + 16384 + 32 * kc);
                LDSM4(bGOh, boffH[npp + 4] + 32 * kc);
                LDSM4(bGOl, boffH[npp + 4] + 16384 + 32 * kc);
                MMA_F16(dIF0, ah[kc], bIFh[0], bIFh[1]);
                MMA_F16(dIF0, ah[kc], bIFl[0], bIFl[1]);
                MMA_F16(dIF0, al[kc], bIFh[0], bIFh[1]);
                MMA_F16(dIF1, ah[kc], bIFh[2], bIFh[3]);
                MMA_F16(dIF1, ah[kc], bIFl[2], bIFl[3]);
                MMA_F16(dIF1, al[kc], bIFh[2], bIFh[3]);
                MMA_F16(dGO0, ah[kc], bGOh[0], bGOh[1]);
                MMA_F16(dGO0, ah[kc], bGOl[0], bGOl[1]);
                MMA_F16(dGO0, al[kc], bGOh[0], bGOh[1]);
                MMA_F16(dGO1, ah[kc], bGOh[2], bGOh[3]);
                MMA_F16(dGO1, ah[kc], bGOl[2], bGOl[3]);
                MMA_F16(dGO1, al[kc], bGOh[2], bGOh[3]);
            }
            const int vA = 8 * npp + q;
            const int vB = vA + 4;
            #pragma unroll
            for (int e = 0; e < 4; e++){
                const float* dif = (e < 2) ? dIF0 : dIF1;
                const float* dgo = (e < 2) ? dGO0 : dGO1;
                int half_ = (e & 1) * 2;
                float zi = dif[half_], zf = dif[half_ + 1];
                float zg = dgo[half_], zo = dgo[half_ + 1];
                float ii = sigt(zi), ff = sigt(zf);
                float gg = tanha(zg), oo = sigt(zo);
                float cv = ff * cst[npp * 4 + e] + ii * gg;
                cst[npp * 4 + e] = cv;
                float h = oo * tanha(cv);
                int v  = (e < 2) ? vA : vB;
                int rw = (e & 1) ? row1 : row0;
                uint32_t off = SWZ((uint32_t)(rw * 128 + v * 2));
                __half hh = __float2half(h);
                __half hl = __float2half(h - __half2float(hh));
                *(__half*)(smc + OFF_AH + off) = hh;
                *(__half*)(smc + OFF_AL + off) = hl;
            }
        }
        __syncwarp();
    }

    // --- zx epilogue: stage Wo (fp32) over the BH region, then GEMV ---
    __syncthreads();
    {
        float4* dst = (float4*)(smc + OFF_BH);
        const float4* src = (const float4*)Wo;   // 32*96 f32 = 768 float4
        for (int i = tid; i < 768; i += 128) dst[i] = src[i];
    }
    __syncthreads();
    {
        const int row = tid >> 1;          // 0..63
        const int cg  = tid & 1;
        const float* wos = (float*)(smc + OFF_BH);
        const float* bos = (float*)(smc + OFF_BO);
        float4 acc[12];
        #pragma unroll
        for (int j = 0; j < 12; j++)
            acc[j] = *(const float4*)(bos + cg * 48 + j * 4);
        #pragma unroll 4
        for (int k = 0; k < 32; k++){
            uint32_t off = SWZ((uint32_t)(row * 128 + k * 2));
            float hk = __half2float(*(__half*)(smc + OFF_AH + off))
                     + __half2float(*(__half*)(smc + OFF_AL + off));
            const float4* wp = (const float4*)(wos + k * 96 + cg * 48);
            #pragma unroll
            for (int j = 0; j < 12; j++){
                float4 w = wp[j];
                acc[j].x = fmaf(hk, w.x, acc[j].x);
                acc[j].y = fmaf(hk, w.y, acc[j].y);
                acc[j].z = fmaf(hk, w.z, acc[j].z);
                acc[j].w = fmaf(hk, w.w, acc[j].w);
            }
        }
        float* zp = g_zx + ((size_t)blockIdx.x * 64 + row) * 96 + cg * 48;
        #pragma unroll
        for (int j = 0; j < 12; j++) *(float4*)(zp + j * 4) = acc[j];
    }
}

// =====================================================================
// Outer LSTM + dense head (R8 version, 93us): one warp per batch row,
// register weights, static depth-2 prefetch, split chains.
// =====================================================================
__device__ __forceinline__ void outer_step(
    float& h, float& c, u64 zA, u64 zB,
    const u64* w_if, const u64* w_go)
{
    u64 a0 = zA, a1 = 0ULL, b0 = zB, b1 = 0ULL;
    #pragma unroll
    for (int j = 0; j < 12; j++){
        float h0 = __shfl_sync(0xffffffffu, h, j);
        float h1 = __shfl_sync(0xffffffffu, h, j + 12);
        u64 H0 = pk2(h0, h0), H1 = pk2(h1, h1);
        a0 = ffma2(H0, w_if[j],      a0);
        b0 = ffma2(H0, w_go[j],      b0);
        a1 = ffma2(H1, w_if[j + 12], a1);
        b1 = ffma2(H1, w_go[j + 12], b1);
    }
    u64 zAf = add2(a0, a1);
    u64 zBf = add2(b0, b1);
    float zi, zf, zg, zo;
    up2(zAf, zi, zf);
    up2(zBf, zg, zo);
    float fi = sigt(zi), ff = sigt(zf), gg = tanha(zg), oo = sigt(zo);
    c = fmaf(ff, c, fi * gg);
    h = oo * tanha(c);
}

__global__ void __launch_bounds__(32) outer_kernel(
    const int*   __restrict__ lengths,
    const float* __restrict__ Uo,
    const float* __restrict__ Wd,
    const float* __restrict__ bd,
    float*       __restrict__ out)
{
    const int l  = threadIdx.x;
    const int la = (l < 24) ? l : 0;
    const int b  = blockIdx.x;

    u64 w_if[24], w_go[24];
    #pragma unroll
    for (int k = 0; k < 24; k++){
        const float* row = Uo + k * 96;
        w_if[k] = pk2(__ldg(row + la),      __ldg(row + 24 + la));
        w_go[k] = pk2(__ldg(row + 48 + la), __ldg(row + 72 + la));
    }

    const int len = lengths[b];
    const float* zr = g_zx + (size_t)b * Tn * 96;

    u64 A0, B0, A1, B1;
    A0 = pk2(zr[la], zr[24 + la]);
    B0 = pk2(zr[48 + la], zr[72 + la]);
    {
        const float* z1 = zr + ((len > 1) ? 96 : 0);
        A1 = pk2(z1[la], z1[24 + la]);
        B1 = pk2(z1[48 + la], z1[72 + la]);
    }

    float h = 0.f, c = 0.f;
    int t = 0;
    while (t < len){
        {
            u64 zA = A0, zB = B0;
            int tp = (t + 2 < len) ? t + 2 : len - 1;
            const float* zq = zr + (size_t)tp * 96;
            A0 = pk2(zq[la], zq[24 + la]);
            B0 = pk2(zq[48 + la], zq[72 + la]);
            outer_step(h, c, zA, zB, w_if, w_go);
        }
        t++;
        if (t >= len) break;
        {
            u64 zA = A1, zB = B1;
            int tp = (t + 2 < len) ? t + 2 : len - 1;
            const float* zq = zr + (size_t)tp * 96;
            A1 = pk2(zq[la], zq[24 + la]);
            B1 = pk2(zq[48 + la], zq[72 + la]);
            outer_step(h, c, zA, zB, w_if, w_go);
        }
        t++;
    }

    float p = (l < 24) ? h * __ldg(Wd + la) : 0.f;
    #pragma unroll
    for (int off = 16; off; off >>= 1) p += __shfl_xor_sync(0xffffffffu, p, off);
    if (l == 0) out[b] = fmaf(0.5f, tanha(0.5f * (p + bd[0])), 0.5f);
}

extern "C" void kernel_launch(void* const* d_in, const int* in_sizes, int n_in,
                              void* d_out, int out_size)
{
    const float* x       = (const float*)d_in[0];
    const int*   lengths = (const int*)  d_in[1];
    const float* Wi      = (const float*)d_in[2];
    const float* Ui      = (const float*)d_in[3];
    const float* bi      = (const float*)d_in[4];
    const float* Wo      = (const float*)d_in[5];
    const float* Uo      = (const float*)d_in[6];
    const float* bo      = (const float*)d_in[7];
    const float* Wd      = (const float*)d_in[8];
    const float* bd      = (const float*)d_in[9];
    float* out = (float*)d_out;

    cudaFuncSetAttribute(inner_mma,
                         cudaFuncAttributeMaxDynamicSharedMemorySize, SMEM_SZ);

    bprep<<<32, 256>>>(Wi, Ui, bi);
    inner_mma<<<1024, 128, SMEM_SZ>>>(x, Wo, bo);
    outer_kernel<<<256, 32>>>(lengths, Uo, Wd, bd, out);
}

// round 11
// speedup vs baseline: 1.2935x; 1.0203x over previous
#include <cuda_runtime.h>
#include <cuda_fp16.h>
#include <cstdint>

typedef unsigned long long u64;

#define Bn 256
#define Tn 256
#define Sn 20
#define NROWS (Bn*Tn)   // 65536

__device__ float g_zx[NROWS * 96];   // zx[row][96] = h_inner[row] @ Wo + bo
__device__ __align__(16) unsigned char g_btiles[32768];  // Bh|Bl fp16, swizzled

// ---------- packed f32x2 helpers (outer kernel) ----------
__device__ __forceinline__ u64 ffma2(u64 a, u64 b, u64 c){
    u64 d;
    asm("fma.rn.f32x2 %0, %1, %2, %3;" : "=l"(d) : "l"(a), "l"(b), "l"(c));
    return d;
}
__device__ __forceinline__ u64 add2(u64 a, u64 b){
    u64 d;
    asm("add.rn.f32x2 %0, %1, %2;" : "=l"(d) : "l"(a), "l"(b));
    return d;
}
__device__ __forceinline__ u64 pk2(float lo, float hi){
    u64 r; asm("mov.b64 %0, {%1, %2};" : "=l"(r) : "f"(lo), "f"(hi)); return r;
}
__device__ __forceinline__ void up2(u64 v, float& lo, float& hi){
    asm("mov.b64 {%0, %1}, %2;" : "=f"(lo), "=f"(hi) : "l"(v));
}

// ---------- activations ----------
__device__ __forceinline__ float tanha(float x){
    float r; asm("tanh.approx.f32 %0, %1;" : "=f"(r) : "f"(x)); return r;
}
__device__ __forceinline__ float sigt(float x){
    return fmaf(0.5f, tanha(0.5f * x), 0.5f);
}

// ---------- smem / swizzle ----------
__device__ __forceinline__ uint32_t smem_to_u32(const void* p){
    uint32_t a;
    asm("{ .reg .u64 t; cvta.to.shared.u64 t, %1; cvt.u32.u64 %0, t; }"
        : "=r"(a) : "l"(p));
    return a;
}
#define SWZ(bo) ((bo) ^ (((bo) >> 3) & 0x70))

// ---------- mma.sync / ldmatrix (fp16, baseline PTX) ----------
#define MMA_F16(d, a, b0v, b1v) \
    asm volatile("mma.sync.aligned.m16n8k16.row.col.f32.f16.f16.f32 " \
        "{%0,%1,%2,%3}, {%4,%5,%6,%7}, {%8,%9}, {%0,%1,%2,%3};" \
        : "+f"((d)[0]), "+f"((d)[1]), "+f"((d)[2]), "+f"((d)[3]) \
        : "r"((a)[0]), "r"((a)[1]), "r"((a)[2]), "r"((a)[3]), "r"(b0v), "r"(b1v))

#define LDSM4(r, addr) \
    asm volatile("ldmatrix.sync.aligned.m8n8.x4.shared.b16 {%0,%1,%2,%3}, [%4];" \
        : "=r"((r)[0]), "=r"((r)[1]), "=r"((r)[2]), "=r"((r)[3]) : "r"(addr))

// SMEM layout (bytes)
#define OFF_AH 0        // A hi [64][64] fp16, 8KB
#define OFF_AL 8192     // A lo, 8KB
#define OFF_BH 16384    // B hi [128][64] fp16, 16KB (Wo fp32 reused here post-loop)
#define OFF_BL 32768    // B lo, 16KB
#define OFF_BO 49152    // bo, 96 f32
#define SMEM_SZ 49664

// =====================================================================
// B-tile prep: build the loop-invariant weight tiles (fp16 hi/lo, SW128-
// swizzled) ONCE in gmem; inner blocks memcpy them (16 LDG.128 iters).
// n-row = permuted gate col ([i,f]x32u | [g,o]x32u), k = [Ui | Wi | bi | 0].
// =====================================================================
__global__ void bprep(const float* __restrict__ Wi,
                      const float* __restrict__ Ui,
                      const float* __restrict__ bi)
{
    int idx = blockIdx.x * 256 + threadIdx.x;
    if (idx >= 8192) return;
    int n = idx >> 6, k = idx & 63;
    int u, g;
    if (n < 64){ u = n >> 1; g = n & 1; }
    else       { u = (n - 64) >> 1; g = 2 + (n & 1); }
    int col = g * 32 + u;
    float w = 0.f;
    if (k < 32)       w = Ui[k * 128 + col];
    else if (k == 32) w = Wi[col];
    else if (k == 33) w = bi[col];
    __half wh = __float2half(w);
    __half wl = __float2half(w - __half2float(wh));
    uint32_t off = SWZ((uint32_t)(n * 128 + k * 2));
    *(__half*)(g_btiles + off)         = wh;
    *(__half*)(g_btiles + 16384 + off) = wl;
}

// =====================================================================
// Inner LSTM via warp-level fp16 mma.sync. 1024 blocks x 128 thr (4 warps),
// 64 rows/block. Warp w owns rows 16w..16w+15 (no block sync in loop).
// Per step: D[16x128] = A[16x48] x B[48x128], 3-product fp16 hi/lo split.
//
// R11 FIX: ldmatrix addresses now apply the SW128 XOR to the FULL in-row
// byte offset (base + 32*kc) instead of adding 32*kc AFTER the swizzle.
// The old form carried into neighboring rows whenever
// (aByte ^ mask) + 32*kc >= 128, silently corrupting the x/1 chunk for
// half the rows (source of the stable 9.1e-4 rel_err in R8-R10).
// =====================================================================
__global__ void __launch_bounds__(128, 4) inner_mma(
    const float* __restrict__ x,
    const float* __restrict__ Wo, const float* __restrict__ bo)
{
    extern __shared__ char smc[];
    const uint32_t sb = smem_to_u32(smc);
    const int tid  = threadIdx.x;
    const int wid  = tid >> 5;
    const int lane = tid & 31;
    const int q    = lane & 3;
    const int rr   = lane >> 2;            // 0..7
    const int wrow0 = wid * 16;            // warp's first local row (0..48)

    // --- copy prebuilt B tiles (32KB contiguous: BH then BL) ---
    {
        const uint4* src = (const uint4*)g_btiles;
        uint4* dst = (uint4*)(smc + OFF_BH);
        for (int i = tid; i < 2048; i += 128) dst[i] = src[i];
    }
    // --- zero A tiles (h0=0, pads=0): 16KB = 4096 u32 ---
    for (int i = tid; i < 4096; i += 128)
        ((uint32_t*)(smc + OFF_AH))[i] = 0u;
    // --- stage bo ---
    if (tid < 96) ((float*)(smc + OFF_BO))[tid] = bo[tid];
    __syncthreads();

    // --- loop-invariant ldmatrix addressing (FULL swizzle per (lane,kc)) ---
    // A tile: row = wrow0 + (lane&15); byte = aByte + 32*kc, aByte in {0,16}
    const uint32_t aRow  = wrow0 + (lane & 15);
    const uint32_t aByte = (uint32_t)(lane >> 4) << 4;
    const uint32_t aMask = (aRow & 7) << 4;
    const uint32_t aBase = sb + OFF_AH + aRow * 128;
    uint32_t akOff[3];
    #pragma unroll
    for (int kc = 0; kc < 3; kc++)
        akOff[kc] = (aByte + 32u * kc) ^ aMask;    // < 128, exact SW128

    // B tile: row = 16*np + nrow; mask depends only on (nrow&7) since 16np==0 mod 8
    uint32_t bBase[8];
    uint32_t bkOff[3];
    {
        uint32_t nrow = ((uint32_t)(lane >> 4) << 3) + (lane & 7);
        uint32_t bbyte = ((uint32_t)((lane >> 3) & 1)) << 4;
        uint32_t bMask = (nrow & 7) << 4;
        #pragma unroll
        for (int np = 0; np < 8; np++)
            bBase[np] = sb + OFF_BH + (16 * np + nrow) * 128;
        #pragma unroll
        for (int kc = 0; kc < 3; kc++)
            bkOff[kc] = (bbyte + 32u * kc) ^ bMask;
    }
    const uint32_t xoff = SWZ((uint32_t)((wrow0 + (lane & 15)) * 128 + 64));

    const long grow = (long)blockIdx.x * 64 + wrow0 + (lane & 15);
    const float* xrow = x + grow * Sn;
    float xnext = __ldg(xrow);

    float cst[16];
    #pragma unroll
    for (int i = 0; i < 16; i++) cst[i] = 0.f;

    const int row0 = wrow0 + rr;
    const int row1 = row0 + 8;

    #pragma unroll 1
    for (int s = 0; s < Sn; s++){
        if (lane < 16){
            float xv = xnext;
            int sp = (s + 1 < Sn) ? s + 1 : s;
            xnext = __ldg(xrow + sp);
            __half xh = __float2half(xv);
            __half xl = __float2half(xv - __half2float(xh));
            // low addr = k=32 (x), high = k=33 (one = fp16 0x3C00)
            uint32_t hi = (0x3C00u << 16) | (uint32_t)__half_as_ushort(xh);
            uint32_t lo = (uint32_t)__half_as_ushort(xl);
            *(uint32_t*)(smc + OFF_AH + xoff) = hi;
            *(uint32_t*)(smc + OFF_AL + xoff) = lo;
        }
        __syncwarp();

        uint32_t ah[3][4], al[3][4];
        #pragma unroll
        for (int kc = 0; kc < 3; kc++){
            LDSM4(ah[kc], aBase + akOff[kc]);
            LDSM4(al[kc], aBase + 8192 + akOff[kc]);
        }
        __syncwarp();

        #pragma unroll
        for (int npp = 0; npp < 4; npp++){
            float dIF0[4] = {0.f,0.f,0.f,0.f};
            float dIF1[4] = {0.f,0.f,0.f,0.f};
            float dGO0[4] = {0.f,0.f,0.f,0.f};
            float dGO1[4] = {0.f,0.f,0.f,0.f};
            #pragma unroll
            for (int kc = 0; kc < 3; kc++){
                uint32_t bIFh[4], bIFl[4], bGOh[4], bGOl[4];
                LDSM4(bIFh, bBase[npp]     + bkOff[kc]);
                LDSM4(bIFl, bBase[npp]     + 16384 + bkOff[kc]);
                LDSM4(bGOh, bBase[npp + 4] + bkOff[kc]);
                LDSM4(bGOl, bBase[npp + 4] + 16384 + bkOff[kc]);
                MMA_F16(dIF0, ah[kc], bIFh[0], bIFh[1]);
                MMA_F16(dIF0, ah[kc], bIFl[0], bIFl[1]);
                MMA_F16(dIF0, al[kc], bIFh[0], bIFh[1]);
                MMA_F16(dIF1, ah[kc], bIFh[2], bIFh[3]);
                MMA_F16(dIF1, ah[kc], bIFl[2], bIFl[3]);
                MMA_F16(dIF1, al[kc], bIFh[2], bIFh[3]);
                MMA_F16(dGO0, ah[kc], bGOh[0], bGOh[1]);
                MMA_F16(dGO0, ah[kc], bGOl[0], bGOl[1]);
                MMA_F16(dGO0, al[kc], bGOh[0], bGOh[1]);
                MMA_F16(dGO1, ah[kc], bGOh[2], bGOh[3]);
                MMA_F16(dGO1, ah[kc], bGOl[2], bGOl[3]);
                MMA_F16(dGO1, al[kc], bGOh[2], bGOh[3]);
            }
            const int vA = 8 * npp + q;
            const int vB = vA + 4;
            #pragma unroll
            for (int e = 0; e < 4; e++){
                const float* dif = (e < 2) ? dIF0 : dIF1;
                const float* dgo = (e < 2) ? dGO0 : dGO1;
                int half_ = (e & 1) * 2;
                float zi = dif[half_], zf = dif[half_ + 1];
                float zg = dgo[half_], zo = dgo[half_ + 1];
                float ii = sigt(zi), ff = sigt(zf);
                float gg = tanha(zg), oo = sigt(zo);
                float cv = ff * cst[npp * 4 + e] + ii * gg;
                cst[npp * 4 + e] = cv;
                float h = oo * tanha(cv);
                int v  = (e < 2) ? vA : vB;
                int rw = (e & 1) ? row1 : row0;
                uint32_t off = SWZ((uint32_t)(rw * 128 + v * 2));
                __half hh = __float2half(h);
                __half hl = __float2half(h - __half2float(hh));
                *(__half*)(smc + OFF_AH + off) = hh;
                *(__half*)(smc + OFF_AL + off) = hl;
            }
        }
        __syncwarp();
    }

    // --- zx epilogue: stage Wo (fp32) over the BH region, then GEMV ---
    __syncthreads();
    {
        float4* dst = (float4*)(smc + OFF_BH);
        const float4* src = (const float4*)Wo;   // 32*96 f32 = 768 float4
        for (int i = tid; i < 768; i += 128) dst[i] = src[i];
    }
    __syncthreads();
    {
        const int row = tid >> 1;          // 0..63
        const int cg  = tid & 1;
        const float* wos = (float*)(smc + OFF_BH);
        const float* bos = (float*)(smc + OFF_BO);
        float4 acc[12];
        #pragma unroll
        for (int j = 0; j < 12; j++)
            acc[j] = *(const float4*)(bos + cg * 48 + j * 4);
        #pragma unroll 4
        for (int k = 0; k < 32; k++){
            uint32_t off = SWZ((uint32_t)(row * 128 + k * 2));
            float hk = __half2float(*(__half*)(smc + OFF_AH + off))
                     + __half2float(*(__half*)(smc + OFF_AL + off));
            const float4* wp = (const float4*)(wos + k * 96 + cg * 48);
            #pragma unroll
            for (int j = 0; j < 12; j++){
                float4 w = wp[j];
                acc[j].x = fmaf(hk, w.x, acc[j].x);
                acc[j].y = fmaf(hk, w.y, acc[j].y);
                acc[j].z = fmaf(hk, w.z, acc[j].z);
                acc[j].w = fmaf(hk, w.w, acc[j].w);
            }
        }
        float* zp = g_zx + ((size_t)blockIdx.x * 64 + row) * 96 + cg * 48;
        #pragma unroll
        for (int j = 0; j < 12; j++) *(float4*)(zp + j * 4) = acc[j];
    }
}

// =====================================================================
// Outer LSTM + dense head (R8 version, 93us): one warp per batch row,
// register weights, static depth-2 prefetch, split chains.
// =====================================================================
__device__ __forceinline__ void outer_step(
    float& h, float& c, u64 zA, u64 zB,
    const u64* w_if, const u64* w_go)
{
    u64 a0 = zA, a1 = 0ULL, b0 = zB, b1 = 0ULL;
    #pragma unroll
    for (int j = 0; j < 12; j++){
        float h0 = __shfl_sync(0xffffffffu, h, j);
        float h1 = __shfl_sync(0xffffffffu, h, j + 12);
        u64 H0 = pk2(h0, h0), H1 = pk2(h1, h1);
        a0 = ffma2(H0, w_if[j],      a0);
        b0 = ffma2(H0, w_go[j],      b0);
        a1 = ffma2(H1, w_if[j + 12], a1);
        b1 = ffma2(H1, w_go[j + 12], b1);
    }
    u64 zAf = add2(a0, a1);
    u64 zBf = add2(b0, b1);
    float zi, zf, zg, zo;
    up2(zAf, zi, zf);
    up2(zBf, zg, zo);
    float fi = sigt(zi), ff = sigt(zf), gg = tanha(zg), oo = sigt(zo);
    c = fmaf(ff, c, fi * gg);
    h = oo * tanha(c);
}

__global__ void __launch_bounds__(32) outer_kernel(
    const int*   __restrict__ lengths,
    const float* __restrict__ Uo,
    const float* __restrict__ Wd,
    const float* __restrict__ bd,
    float*       __restrict__ out)
{
    const int l  = threadIdx.x;
    const int la = (l < 24) ? l : 0;
    const int b  = blockIdx.x;

    u64 w_if[24], w_go[24];
    #pragma unroll
    for (int k = 0; k < 24; k++){
        const float* row = Uo + k * 96;
        w_if[k] = pk2(__ldg(row + la),      __ldg(row + 24 + la));
        w_go[k] = pk2(__ldg(row + 48 + la), __ldg(row + 72 + la));
    }

    const int len = lengths[b];
    const float* zr = g_zx + (size_t)b * Tn * 96;

    u64 A0, B0, A1, B1;
    A0 = pk2(zr[la], zr[24 + la]);
    B0 = pk2(zr[48 + la], zr[72 + la]);
    {
        const float* z1 = zr + ((len > 1) ? 96 : 0);
        A1 = pk2(z1[la], z1[24 + la]);
        B1 = pk2(z1[48 + la], z1[72 + la]);
    }

    float h = 0.f, c = 0.f;
    int t = 0;
    while (t < len){
        {
            u64 zA = A0, zB = B0;
            int tp = (t + 2 < len) ? t + 2 : len - 1;
            const float* zq = zr + (size_t)tp * 96;
            A0 = pk2(zq[la], zq[24 + la]);
            B0 = pk2(zq[48 + la], zq[72 + la]);
            outer_step(h, c, zA, zB, w_if, w_go);
        }
        t++;
        if (t >= len) break;
        {
            u64 zA = A1, zB = B1;
            int tp = (t + 2 < len) ? t + 2 : len - 1;
            const float* zq = zr + (size_t)tp * 96;
            A1 = pk2(zq[la], zq[24 + la]);
            B1 = pk2(zq[48 + la], zq[72 + la]);
            outer_step(h, c, zA, zB, w_if, w_go);
        }
        t++;
    }

    float p = (l < 24) ? h * __ldg(Wd + la) : 0.f;
    #pragma unroll
    for (int off = 16; off; off >>= 1) p += __shfl_xor_sync(0xffffffffu, p, off);
    if (l == 0) out[b] = fmaf(0.5f, tanha(0.5f * (p + bd[0])), 0.5f);
}

extern "C" void kernel_launch(void* const* d_in, const int* in_sizes, int n_in,
                              void* d_out, int out_size)
{
    const float* x       = (const float*)d_in[0];
    const int*   lengths = (const int*)  d_in[1];
    const float* Wi      = (const float*)d_in[2];
    const float* Ui      = (const float*)d_in[3];
    const float* bi      = (const float*)d_in[4];
    const float* Wo      = (const float*)d_in[5];
    const float* Uo      = (const float*)d_in[6];
    const float* bo      = (const float*)d_in[7];
    const float* Wd      = (const float*)d_in[8];
    const float* bd      = (const float*)d_in[9];
    float* out = (float*)d_out;

    cudaFuncSetAttribute(inner_mma,
                         cudaFuncAttributeMaxDynamicSharedMemorySize, SMEM_SZ);

    bprep<<<32, 256>>>(Wi, Ui, bi);
    inner_mma<<<1024, 128, SMEM_SZ>>>(x, Wo, bo);
    outer_kernel<<<256, 32>>>(lengths, Uo, Wd, bd, out);
}